// round 2
// baseline (speedup 1.0000x reference)
#include <cuda_runtime.h>
#include <cuda_bf16.h>

#define N_NODES 50000
#define N_EDGES 800000
#define D       64
#define ROWS    128   // rows per block in the dense kernel

// Scratch: neighbor aggregation buffer (no cudaMalloc allowed)
__device__ float g_neigh[N_NODES * D];

// ---------------------------------------------------------------------------
// helpers
// ---------------------------------------------------------------------------
__device__ __forceinline__ void red_add_v4(float* p, float a, float b, float c, float d) {
    asm volatile("red.global.add.v4.f32 [%0], {%1, %2, %3, %4};"
                 :: "l"(p), "f"(a), "f"(b), "f"(c), "f"(d) : "memory");
}

// packed fp32x2 FMA: d = a*b + d   (Blackwell double-rate fp32 path)
__device__ __forceinline__ void ffma2(unsigned long long& d,
                                      unsigned long long a,
                                      unsigned long long b) {
    asm("fma.rn.f32x2 %0, %1, %2, %0;" : "+l"(d) : "l"(a), "l"(b));
}

__device__ __forceinline__ unsigned long long pack2(float x) {
    unsigned long long r;
    unsigned int xi = __float_as_uint(x);
    asm("mov.b64 %0, {%1, %1};" : "=l"(r) : "r"(xi));
    return r;
}

__device__ __forceinline__ void unpack2(unsigned long long v, float& lo, float& hi) {
    unsigned int a, b;
    asm("mov.b64 {%0, %1}, %2;" : "=r"(a), "=r"(b) : "l"(v));
    lo = __uint_as_float(a);
    hi = __uint_as_float(b);
}

// ---------------------------------------------------------------------------
// Kernel 1: zero the aggregation buffer (vectorized)
// ---------------------------------------------------------------------------
__global__ void zero_kernel() {
    int i = blockIdx.x * blockDim.x + threadIdx.x;
    float4* p = reinterpret_cast<float4*>(g_neigh);
    if (i < (N_NODES * D) / 4) p[i] = make_float4(0.f, 0.f, 0.f, 0.f);
}

// ---------------------------------------------------------------------------
// Kernel 2: scatter  g_neigh[dst] += w * h[src]
// 4 threads per edge; each thread does 4x (LDG.128 -> RED.v4).
// Per-instruction layout: lanes of one edge cover a contiguous 64B chunk,
// so each warp-level LDG/RED touches 8 lines (one per edge), and the
// edge-index loads amortize over 4x fewer warps than the 16-lane version.
// ---------------------------------------------------------------------------
__global__ void scatter_kernel(const float* __restrict__ h,
                               const int*   __restrict__ src,
                               const int*   __restrict__ dst,
                               const float* __restrict__ w) {
    int t = blockIdx.x * blockDim.x + threadIdx.x;
    int e    = t >> 2;
    int lane = t & 3;
    if (e >= N_EDGES) return;

    int   s  = __ldg(src + e);
    int   d  = __ldg(dst + e);
    float wt = __ldg(w + e);

    const float4* hp = reinterpret_cast<const float4*>(h + (size_t)s * D);
    float*        np = g_neigh + (size_t)d * D;

    float4 v[4];
#pragma unroll
    for (int i = 0; i < 4; i++) v[i] = __ldg(hp + lane + 4 * i);   // MLP=4

#pragma unroll
    for (int i = 0; i < 4; i++) {
        red_add_v4(np + (lane + 4 * i) * 4,
                   v[i].x * wt, v[i].y * wt, v[i].z * wt, v[i].w * wt);
    }
}

// ---------------------------------------------------------------------------
// Kernel 3: dense  out = relu([h | neigh] @ [W_self | W_neigh]^T + b_self + b_neigh)
// One thread per output row; 64 fp32 accumulators packed as 32 b64 regs,
// updated with fma.rn.f32x2 (2 FMAs/issue). Weight pairs read as broadcast
// LDS.128 (ulonglong2 -> two packed operands per shared load).
// ---------------------------------------------------------------------------
__global__ __launch_bounds__(ROWS)
void dense_kernel(const float* __restrict__ h,
                  const float* __restrict__ Ws, const float* __restrict__ bs,
                  const float* __restrict__ Wn, const float* __restrict__ bn,
                  float* __restrict__ out) {
    __shared__ __align__(16) float sW[128 * 64];  // sW[k*64+j]; k<64 self, k>=64 neigh
    __shared__ float sX[32][ROWS + 1];            // stride 129: conflict-free transpose
    __shared__ float sB[64];

    const int tid     = threadIdx.x;
    const int rowBase = blockIdx.x * ROWS;
    const int row     = rowBase + tid;
    const bool valid  = row < N_NODES;

    // Load combined W^T: sW[k][j] = W[j][k]
    for (int idx = tid; idx < 128 * 64; idx += ROWS) {
        int k = idx >> 6, j = idx & 63;
        sW[idx] = (k < 64) ? Ws[j * 64 + k] : Wn[j * 64 + (k - 64)];
    }
    if (tid < 64) sB[tid] = bs[tid] + bn[tid];

    unsigned long long acc[32];
#pragma unroll
    for (int p = 0; p < 32; p++) acc[p] = 0ull;

    const int lane = tid & 31;   // k offset within chunk (coalesced load dim)
    const int rq   = tid >> 5;   // row phase

    for (int kc = 0; kc < 4; kc++) {
        const float* srcp = (kc < 2) ? h : g_neigh;
        const int colBase = (kc & 1) * 32;

        __syncthreads();  // protect sX reuse (covers sW/sB on first iter)

        // Stage: sX[k][r] = x[rowBase + r][kc*32 + k], coalesced global reads
        for (int r = rq; r < ROWS; r += ROWS / 32) {
            int rr = rowBase + r;
            float val = (rr < N_NODES) ? srcp[(size_t)rr * D + colBase + lane] : 0.f;
            sX[lane][r] = val;
        }
        __syncthreads();

#pragma unroll 4
        for (int kk = 0; kk < 32; kk++) {
            unsigned long long xx = pack2(sX[kk][tid]);
            const ulonglong2* wrow = reinterpret_cast<const ulonglong2*>(
                sW + (kc * 32 + kk) * 64);
#pragma unroll
            for (int q = 0; q < 16; q++) {
                ulonglong2 wv = wrow[q];      // broadcast LDS.128 -> 2 packed pairs
                ffma2(acc[2 * q + 0], xx, wv.x);
                ffma2(acc[2 * q + 1], xx, wv.y);
            }
        }
    }

    if (valid) {
        float4* op = reinterpret_cast<float4*>(out + (size_t)row * D);
#pragma unroll
        for (int q4 = 0; q4 < 16; q4++) {
            float a, b, c, d;
            unpack2(acc[2 * q4 + 0], a, b);
            unpack2(acc[2 * q4 + 1], c, d);
            float4 o;
            o.x = fmaxf(a + sB[4 * q4 + 0], 0.f);
            o.y = fmaxf(b + sB[4 * q4 + 1], 0.f);
            o.z = fmaxf(c + sB[4 * q4 + 2], 0.f);
            o.w = fmaxf(d + sB[4 * q4 + 3], 0.f);
            op[q4] = o;
        }
    }
}

// ---------------------------------------------------------------------------
// kernel_launch: inputs per reference order
//   0: h [N,D] f32   1: edge_src [E] i32   2: edge_dst [E] i32   3: edge_w [E] f32
//   4: W_self [D,D]  5: b_self [D]         6: W_neigh [D,D]      7: b_neigh [D]
// ---------------------------------------------------------------------------
extern "C" void kernel_launch(void* const* d_in, const int* in_sizes, int n_in,
                              void* d_out, int out_size) {
    const float* h        = (const float*)d_in[0];
    const int*   edge_src = (const int*)  d_in[1];
    const int*   edge_dst = (const int*)  d_in[2];
    const float* edge_w   = (const float*)d_in[3];
    const float* W_self   = (const float*)d_in[4];
    const float* b_self   = (const float*)d_in[5];
    const float* W_neigh  = (const float*)d_in[6];
    const float* b_neigh  = (const float*)d_in[7];
    float* out = (float*)d_out;

    // 1) zero aggregation buffer
    {
        int n4 = (N_NODES * D) / 4;
        zero_kernel<<<(n4 + 511) / 512, 512>>>();
    }

    // 2) scatter: 4 threads/edge
    {
        long long total = (long long)N_EDGES * 4;
        int threads = 256;
        int blocks = (int)((total + threads - 1) / threads);
        scatter_kernel<<<blocks, threads>>>(h, edge_src, edge_dst, edge_w);
    }

    // 3) fused dense + bias + relu
    {
        int blocks = (N_NODES + ROWS - 1) / ROWS;
        dense_kernel<<<blocks, ROWS>>>(h, W_self, b_self, W_neigh, b_neigh, out);
    }
}